// round 13
// baseline (speedup 1.0000x reference)
#include <cuda_runtime.h>
#include <cuda_fp16.h>
#include <cstdint>

// Problem constants
#define Bsz 256      // batch (GEMM M)
#define Isz 128      // in_units
#define Csz 1024     // in_channels
#define Nsz 512      // U*S (GEMM N)
#define NSPLIT 32    // split-K slices -> grid (2,2,32) = 128 CTAs = 1 wave
#define CPS (Csz / NSPLIT)      // 32 c per slice
#define KSLICE (CPS * Isz)      // 4096 k per slice
#define BK 32                   // k per stage (2 x k16 MMA steps)
#define NSTAGE (KSLICE / BK)    // 128 stages

// CTA tile 128x256, 8 warps (2x4), warp tile 64x64
#define BM 128
#define BN 256

// smem rows padded to 40 halfs (80 B) -> conflict-free fragment loads
#define RSTRIDE 40
#define A_HALFS (BM * RSTRIDE)              // 5120
#define B_HALFS (BN * RSTRIDE)              // 10240
#define STG_HALFS (A_HALFS + B_HALFS)       // 15360
#define SMEM_BYTES (2 * STG_HALFS * 2)      // 61440

// Scratch (static device globals — no runtime allocation)
__device__ __half g_xh[(size_t)Bsz * Csz * Isz];       // x^T (b, c, i) in fp16
__device__ float  g_part[(size_t)NSPLIT * Bsz * Nsz];  // split-K partials

// ---------------------------------------------------------------------------
// Helpers (sm_70/80-era PTX only — target is compute_103 WITHOUT 'a')
// ---------------------------------------------------------------------------
__device__ __forceinline__ uint32_t smem_u32(const void* p) {
    uint32_t a;
    asm("{ .reg .u64 t; cvta.to.shared.u64 t, %1; cvt.u32.u64 %0, t; }" : "=r"(a) : "l"(p));
    return a;
}

#define CP_ASYNC16(dst, src) \
    asm volatile("cp.async.cg.shared.global [%0], [%1], 16;" :: "r"(dst), "l"(src))
#define CP_COMMIT()  asm volatile("cp.async.commit_group;" ::: "memory")
#define CP_WAIT(n)   asm volatile("cp.async.wait_group %0;" :: "n"(n) : "memory")

// m16n8k16 fp16 MMA, fp32 accumulate (sm_70 base PTX)
#define MMA_F16(c, a, b) \
    asm volatile( \
        "mma.sync.aligned.m16n8k16.row.col.f32.f16.f16.f32 " \
        "{%0,%1,%2,%3}, {%4,%5,%6,%7}, {%8,%9}, {%0,%1,%2,%3};" \
        : "+f"((c)[0]), "+f"((c)[1]), "+f"((c)[2]), "+f"((c)[3]) \
        : "r"((a)[0]), "r"((a)[1]), "r"((a)[2]), "r"((a)[3]), \
          "r"((b)[0]), "r"((b)[1]))

// ---------------------------------------------------------------------------
// Kernel 1: per-batch transpose x (B, I, C) -> xh (B, C, I) in fp16
//   Block: 256 threads (32, 8). Tile: 64 i x 32 c per block.
//   Loads: 128 B coalesced per warp. Stores: uint2 (4 halfs) per thread ->
//   16 lanes x 8 B = full 128 B store transactions.
// ---------------------------------------------------------------------------
__global__ void k_transpose(const float* __restrict__ x) {
    __shared__ float tile[64][33];   // [i][c]
    const int b  = blockIdx.z;
    const int c0 = blockIdx.x * 32;
    const int i0 = blockIdx.y * 64;
    const float* xb  = x    + (size_t)b * Isz * Csz;
    __half*      xtb = g_xh + (size_t)b * Csz * Isz;
    const int tx = threadIdx.x, ty = threadIdx.y;

    // load 64 rows (i) x 32 cols (c)
#pragma unroll
    for (int j = 0; j < 8; j++)
        tile[ty + j * 8][tx] = xb[(size_t)(i0 + ty + j * 8) * Csz + (c0 + tx)];
    __syncthreads();

    // store: each thread emits 4 consecutive i as 2x half2 (one uint2 8B store)
    const int k  = tx & 15;   // i-quad index (0..15) -> i = 4k
    const int ch = tx >> 4;   // 0..1 extra c
#pragma unroll
    for (int j = 0; j < 2; j++) {
        const int cc = 2 * ty + ch + j * 16;     // 0..31
        const int ii = 4 * k;
        __half2 h0 = __floats2half2_rn(tile[ii + 0][cc], tile[ii + 1][cc]);
        __half2 h1 = __floats2half2_rn(tile[ii + 2][cc], tile[ii + 3][cc]);
        __half2* dst = (__half2*)(xtb + (size_t)(c0 + cc) * Isz + (i0 + ii));
        dst[0] = h0;
        dst[1] = h1;
    }
}

// ---------------------------------------------------------------------------
// Kernel 2: split-K fp16 GEMM via mma.sync m16n8k16 (fp32 accum)
//   grid = (2 m, 2 n, 32 slices) = 128 CTAs; CTA 128x256; warp tile 64x64
//   A (fp16) via cp.async; B from W fp32 via LDG.128 -> cvt -> STS.64
// ---------------------------------------------------------------------------
__global__ __launch_bounds__(256, 1)
void k_gemm_mma(const float* __restrict__ W) {
    extern __shared__ __half sm[];
    const uint32_t smem_base = smem_u32(sm);

    const int tid  = threadIdx.x;
    const int wid  = tid >> 5;
    const int lane = tid & 31;
    const int g    = lane >> 2;   // group id (0..7)
    const int t    = lane & 3;    // thread-in-group

    const int warp_m = wid & 1;   // 0..1 -> 64-row block
    const int warp_n = wid >> 1;  // 0..3 -> 64-col block

    const int m0 = blockIdx.x * BM;
    const int n0 = blockIdx.y * BN;
    const int c0 = blockIdx.z * CPS;

    const __half* aBase = g_xh + (size_t)m0 * (Csz * Isz) + (size_t)c0 * Isz;
    const float*  wBase = W + (size_t)c0 * (Nsz * Isz) + (size_t)n0 * Isz;

    // A loader indices: 128 rows x 4 chunks of 16B (8 halfs)
    const int a_row = tid >> 2;   // 0..63 (+64 on j=1)
    const int a_ch  = tid & 3;    // 16B chunk
    // B loader indices: 256 rows x 8 chunks of float4 (4 floats -> 4 halfs)
    const int b_row = tid >> 3;   // 0..31 (+32*j)
    const int b_ch  = tid & 7;

    auto a_issue = [&](int st, int bf) {
        const uint32_t dA = smem_base + (uint32_t)(bf * STG_HALFS) * 2;
        const __half* asrc = aBase + st * BK;
#pragma unroll
        for (int j = 0; j < 2; j++) {
            int r = a_row + j * 64;
            uint32_t so = (uint32_t)(r * RSTRIDE + a_ch * 8) * 2;
            CP_ASYNC16(dA + so, asrc + (size_t)r * (Csz * Isz) + a_ch * 8);
        }
        CP_COMMIT();
    };

    float4 bpf[8];
    auto b_ldg = [&](int st) {
        const float* bsrc = wBase + (size_t)(st >> 2) * (Nsz * Isz) + (st & 3) * BK;
#pragma unroll
        for (int j = 0; j < 8; j++) {
            int r = b_row + j * 32;
            bpf[j] = *(const float4*)(bsrc + (size_t)r * Isz + b_ch * 4);
        }
    };
    auto b_sts = [&](int bf) {
        __half* dB = sm + bf * STG_HALFS + A_HALFS;
#pragma unroll
        for (int j = 0; j < 8; j++) {
            int r = b_row + j * 32;
            __half2 p0 = __floats2half2_rn(bpf[j].x, bpf[j].y);
            __half2 p1 = __floats2half2_rn(bpf[j].z, bpf[j].w);
            *(__half2*)(dB + r * RSTRIDE + b_ch * 4)     = p0;
            *(__half2*)(dB + r * RSTRIDE + b_ch * 4 + 2) = p1;
        }
    };

    float acc[4][8][4];
#pragma unroll
    for (int mt = 0; mt < 4; mt++)
#pragma unroll
        for (int nt = 0; nt < 8; nt++)
#pragma unroll
            for (int e = 0; e < 4; e++) acc[mt][nt][e] = 0.f;

    // prologue: stage 0
    b_ldg(0);
    a_issue(0, 0);
    b_sts(0);
    CP_WAIT(0);
    __syncthreads();
    int buf = 0;

    for (int st = 0; st < NSTAGE; ++st) {
        const bool has_next = (st + 1 < NSTAGE);
        if (has_next) {
            b_ldg(st + 1);            // LDG latency overlapped by compute below
            a_issue(st + 1, buf ^ 1);
        }

        const __half* cA = sm + buf * STG_HALFS;
        const __half* cB = cA + A_HALFS;

#pragma unroll
        for (int kk = 0; kk < 2; ++kk) {
            const int kb = kk * 16;
            uint32_t af[4][4];
#pragma unroll
            for (int mt = 0; mt < 4; mt++) {
                const int r0 = warp_m * 64 + mt * 16 + g;
                const __half* p0 = cA + r0 * RSTRIDE + kb + 2 * t;
                const __half* p1 = cA + (r0 + 8) * RSTRIDE + kb + 2 * t;
                af[mt][0] = *(const uint32_t*)p0;
                af[mt][1] = *(const uint32_t*)p1;
                af[mt][2] = *(const uint32_t*)(p0 + 8);
                af[mt][3] = *(const uint32_t*)(p1 + 8);
            }
            uint32_t bfr[8][2];
#pragma unroll
            for (int nt = 0; nt < 8; nt++) {
                const int nn = warp_n * 64 + nt * 8 + g;
                const __half* p = cB + nn * RSTRIDE + kb + 2 * t;
                bfr[nt][0] = *(const uint32_t*)p;
                bfr[nt][1] = *(const uint32_t*)(p + 8);
            }
#pragma unroll
            for (int mt = 0; mt < 4; mt++)
#pragma unroll
                for (int nt = 0; nt < 8; nt++)
                    MMA_F16(acc[mt][nt], af[mt], bfr[nt]);
        }

        if (has_next) {
            b_sts(buf ^ 1);
            CP_WAIT(0);
        }
        __syncthreads();
        buf ^= 1;
    }

    // epilogue: deterministic partial writes
    float* dst = g_part + (size_t)blockIdx.z * (Bsz * Nsz);
#pragma unroll
    for (int mt = 0; mt < 4; mt++) {
        const int m = m0 + warp_m * 64 + mt * 16 + g;
#pragma unroll
        for (int nt = 0; nt < 8; nt++) {
            const int n = n0 + warp_n * 64 + nt * 8 + 2 * t;
            *(float2*)&dst[(size_t)m * Nsz + n] =
                make_float2(acc[mt][nt][0], acc[mt][nt][1]);
            *(float2*)&dst[(size_t)(m + 8) * Nsz + n] =
                make_float2(acc[mt][nt][2], acc[mt][nt][3]);
        }
    }
}

// ---------------------------------------------------------------------------
// Kernel 3: reduce over split-K slices + squash epilogue
// ---------------------------------------------------------------------------
__global__ void k_reduce_squash(float* __restrict__ out) {
    const int b = blockIdx.x;
    const int n = threadIdx.x;  // 0..511
    float s = 0.f;
    const float* p = g_part + (size_t)b * Nsz + n;
#pragma unroll 8
    for (int sl = 0; sl < NSPLIT; ++sl)
        s += p[(size_t)sl * (Bsz * Nsz)];

    __shared__ float sv[Nsz];
    sv[n] = s;
    __syncthreads();

    const int sidx = n & 15;
    float msq = 0.f;
#pragma unroll
    for (int u = 0; u < 32; ++u) {
        float v = sv[u * 16 + sidx];
        msq += v * v;
    }
    const float mag   = sqrtf(msq);
    const float scale = mag / (1.0f + msq);
    out[(size_t)b * Nsz + n] = s * scale;
}

// ---------------------------------------------------------------------------
extern "C" void kernel_launch(void* const* d_in, const int* in_sizes, int n_in,
                              void* d_out, int out_size) {
    const float* x = (const float*)d_in[0];   // (256, 128, 1024) fp32
    const float* W = (const float*)d_in[1];   // (1, 1024, 32, 16, 128) fp32
    float* out = (float*)d_out;               // (256, 32, 16, 1) fp32

    static bool attr_done = false;
    if (!attr_done) {
        cudaFuncSetAttribute(k_gemm_mma, cudaFuncAttributeMaxDynamicSharedMemorySize,
                             SMEM_BYTES);
        attr_done = true;
    }

    dim3 tgrid(Csz / 32, Isz / 64, Bsz);      // (32, 2, 256)
    k_transpose<<<tgrid, dim3(32, 8)>>>(x);

    dim3 ggrid(Bsz / BM, Nsz / BN, NSPLIT);   // (2, 2, 32) = 128 CTAs
    k_gemm_mma<<<ggrid, 256, SMEM_BYTES>>>(W);

    k_reduce_squash<<<Bsz, Nsz>>>(out);
}

// round 14
// speedup vs baseline: 1.4704x; 1.4704x over previous
#include <cuda_runtime.h>
#include <cuda_fp16.h>
#include <cstdint>

// Problem constants
#define Bsz 256      // batch (GEMM M)
#define Isz 128      // in_units
#define Csz 1024     // in_channels
#define Nsz 512      // U*S (GEMM N)
#define NSPLIT 32    // split-K slices -> grid (2,2,32) = 128 CTAs = 1 wave
#define CPS (Csz / NSPLIT)      // 32 c per slice
#define KSLICE (CPS * Isz)      // 4096 k per slice
#define BK 32                   // k per stage (2 x k16 MMA steps)
#define NSTAGE (KSLICE / BK)    // 128 stages

// CTA tile 128x256, 8 warps (2x4), warp tile 64x64
#define BM 128
#define BN 256

// smem rows padded to 40 halfs (80 B) -> conflict-free fragment loads
#define RSTRIDE 40
#define A_HALFS (BM * RSTRIDE)              // 5120
#define B_HALFS (BN * RSTRIDE)              // 10240
#define STG_HALFS (A_HALFS + B_HALFS)       // 15360
#define SMEM_BYTES (2 * STG_HALFS * 2)      // 61440

// Scratch (static device globals — no runtime allocation)
__device__ __half g_xh[(size_t)Bsz * Csz * Isz];       // x^T (b, c, i) in fp16
__device__ float  g_part[(size_t)NSPLIT * Bsz * Nsz];  // split-K partials

// ---------------------------------------------------------------------------
// Helpers (sm_70/80-era PTX only — target is compute_103 WITHOUT 'a')
// ---------------------------------------------------------------------------
__device__ __forceinline__ uint32_t smem_u32(const void* p) {
    uint32_t a;
    asm("{ .reg .u64 t; cvta.to.shared.u64 t, %1; cvt.u32.u64 %0, t; }" : "=r"(a) : "l"(p));
    return a;
}

#define CP_ASYNC16(dst, src) \
    asm volatile("cp.async.cg.shared.global [%0], [%1], 16;" :: "r"(dst), "l"(src))
#define CP_COMMIT()  asm volatile("cp.async.commit_group;" ::: "memory")
#define CP_WAIT(n)   asm volatile("cp.async.wait_group %0;" :: "n"(n) : "memory")

// m16n8k16 fp16 MMA, fp32 accumulate (sm_70 base PTX)
#define MMA_F16(c, a, b) \
    asm volatile( \
        "mma.sync.aligned.m16n8k16.row.col.f32.f16.f16.f32 " \
        "{%0,%1,%2,%3}, {%4,%5,%6,%7}, {%8,%9}, {%0,%1,%2,%3};" \
        : "+f"((c)[0]), "+f"((c)[1]), "+f"((c)[2]), "+f"((c)[3]) \
        : "r"((a)[0]), "r"((a)[1]), "r"((a)[2]), "r"((a)[3]), \
          "r"((b)[0]), "r"((b)[1]))

// ---------------------------------------------------------------------------
// Kernel 1: per-batch transpose x (B, I, C) -> xh (B, C, I) in fp16
//   32x32 tile, 33-float padded rows: both the row-write (along tx) and the
//   column-read (stride 33) phases are bank-conflict-free.
// ---------------------------------------------------------------------------
__global__ void k_transpose(const float* __restrict__ x) {
    __shared__ float tile[32][33];
    int b  = blockIdx.z;
    int c0 = blockIdx.x * 32;
    int i0 = blockIdx.y * 32;
    const float* xb  = x    + (size_t)b * Isz * Csz;
    __half*      xtb = g_xh + (size_t)b * Csz * Isz;
    int tx = threadIdx.x, ty = threadIdx.y;
#pragma unroll
    for (int j = 0; j < 32; j += 8)
        tile[ty + j][tx] = xb[(size_t)(i0 + ty + j) * Csz + (c0 + tx)];
    __syncthreads();
#pragma unroll
    for (int j = 0; j < 32; j += 8)
        xtb[(size_t)(c0 + ty + j) * Isz + (i0 + tx)] = __float2half_rn(tile[tx][ty + j]);
}

// ---------------------------------------------------------------------------
// Kernel 2: split-K fp16 GEMM via mma.sync m16n8k16 (fp32 accum)
//   grid = (2 m, 2 n, 32 slices) = 128 CTAs; CTA 128x256; warp tile 64x64
//   A (fp16) via cp.async; B from W fp32 via LDG.128 -> cvt -> STS.64
// ---------------------------------------------------------------------------
__global__ __launch_bounds__(256, 1)
void k_gemm_mma(const float* __restrict__ W) {
    extern __shared__ __half sm[];
    const uint32_t smem_base = smem_u32(sm);

    const int tid  = threadIdx.x;
    const int wid  = tid >> 5;
    const int lane = tid & 31;
    const int g    = lane >> 2;   // group id (0..7)
    const int t    = lane & 3;    // thread-in-group

    const int warp_m = wid & 1;   // 0..1 -> 64-row block
    const int warp_n = wid >> 1;  // 0..3 -> 64-col block

    const int m0 = blockIdx.x * BM;
    const int n0 = blockIdx.y * BN;
    const int c0 = blockIdx.z * CPS;

    const __half* aBase = g_xh + (size_t)m0 * (Csz * Isz) + (size_t)c0 * Isz;
    const float*  wBase = W + (size_t)c0 * (Nsz * Isz) + (size_t)n0 * Isz;

    // A loader indices: 128 rows x 4 chunks of 16B (8 halfs)
    const int a_row = tid >> 2;   // 0..63 (+64 on j=1)
    const int a_ch  = tid & 3;    // 16B chunk
    // B loader indices: 256 rows x 8 chunks of float4 (4 floats -> 4 halfs)
    const int b_row = tid >> 3;   // 0..31 (+32*j)
    const int b_ch  = tid & 7;

    auto a_issue = [&](int st, int bf) {
        const uint32_t dA = smem_base + (uint32_t)(bf * STG_HALFS) * 2;
        const __half* asrc = aBase + st * BK;
#pragma unroll
        for (int j = 0; j < 2; j++) {
            int r = a_row + j * 64;
            uint32_t so = (uint32_t)(r * RSTRIDE + a_ch * 8) * 2;
            CP_ASYNC16(dA + so, asrc + (size_t)r * (Csz * Isz) + a_ch * 8);
        }
        CP_COMMIT();
    };

    float4 bpf[8];
    auto b_ldg = [&](int st) {
        const float* bsrc = wBase + (size_t)(st >> 2) * (Nsz * Isz) + (st & 3) * BK;
#pragma unroll
        for (int j = 0; j < 8; j++) {
            int r = b_row + j * 32;
            bpf[j] = *(const float4*)(bsrc + (size_t)r * Isz + b_ch * 4);
        }
    };
    auto b_sts = [&](int bf) {
        __half* dB = sm + bf * STG_HALFS + A_HALFS;
#pragma unroll
        for (int j = 0; j < 8; j++) {
            int r = b_row + j * 32;
            __half2 p0 = __floats2half2_rn(bpf[j].x, bpf[j].y);
            __half2 p1 = __floats2half2_rn(bpf[j].z, bpf[j].w);
            *(__half2*)(dB + r * RSTRIDE + b_ch * 4)     = p0;
            *(__half2*)(dB + r * RSTRIDE + b_ch * 4 + 2) = p1;
        }
    };

    float acc[4][8][4];
#pragma unroll
    for (int mt = 0; mt < 4; mt++)
#pragma unroll
        for (int nt = 0; nt < 8; nt++)
#pragma unroll
            for (int e = 0; e < 4; e++) acc[mt][nt][e] = 0.f;

    // prologue: stage 0
    b_ldg(0);
    a_issue(0, 0);
    b_sts(0);
    CP_WAIT(0);
    __syncthreads();
    int buf = 0;

    for (int st = 0; st < NSTAGE; ++st) {
        const bool has_next = (st + 1 < NSTAGE);
        if (has_next) {
            b_ldg(st + 1);            // LDG latency overlapped by compute below
            a_issue(st + 1, buf ^ 1);
        }

        const __half* cA = sm + buf * STG_HALFS;
        const __half* cB = cA + A_HALFS;

#pragma unroll
        for (int kk = 0; kk < 2; ++kk) {
            const int kb = kk * 16;
            uint32_t af[4][4];
#pragma unroll
            for (int mt = 0; mt < 4; mt++) {
                const int r0 = warp_m * 64 + mt * 16 + g;
                const __half* p0 = cA + r0 * RSTRIDE + kb + 2 * t;
                const __half* p1 = cA + (r0 + 8) * RSTRIDE + kb + 2 * t;
                af[mt][0] = *(const uint32_t*)p0;
                af[mt][1] = *(const uint32_t*)p1;
                af[mt][2] = *(const uint32_t*)(p0 + 8);
                af[mt][3] = *(const uint32_t*)(p1 + 8);
            }
            uint32_t bfr[8][2];
#pragma unroll
            for (int nt = 0; nt < 8; nt++) {
                const int nn = warp_n * 64 + nt * 8 + g;
                const __half* p = cB + nn * RSTRIDE + kb + 2 * t;
                bfr[nt][0] = *(const uint32_t*)p;
                bfr[nt][1] = *(const uint32_t*)(p + 8);
            }
#pragma unroll
            for (int mt = 0; mt < 4; mt++)
#pragma unroll
                for (int nt = 0; nt < 8; nt++)
                    MMA_F16(acc[mt][nt], af[mt], bfr[nt]);
        }

        if (has_next) {
            b_sts(buf ^ 1);
            CP_WAIT(0);
        }
        __syncthreads();
        buf ^= 1;
    }

    // epilogue: deterministic partial writes
    float* dst = g_part + (size_t)blockIdx.z * (Bsz * Nsz);
#pragma unroll
    for (int mt = 0; mt < 4; mt++) {
        const int m = m0 + warp_m * 64 + mt * 16 + g;
#pragma unroll
        for (int nt = 0; nt < 8; nt++) {
            const int n = n0 + warp_n * 64 + nt * 8 + 2 * t;
            *(float2*)&dst[(size_t)m * Nsz + n] =
                make_float2(acc[mt][nt][0], acc[mt][nt][1]);
            *(float2*)&dst[(size_t)(m + 8) * Nsz + n] =
                make_float2(acc[mt][nt][2], acc[mt][nt][3]);
        }
    }
}

// ---------------------------------------------------------------------------
// Kernel 3: reduce over split-K slices + squash epilogue
// ---------------------------------------------------------------------------
__global__ void k_reduce_squash(float* __restrict__ out) {
    const int b = blockIdx.x;
    const int n = threadIdx.x;  // 0..511
    float s = 0.f;
    const float* p = g_part + (size_t)b * Nsz + n;
#pragma unroll 8
    for (int sl = 0; sl < NSPLIT; ++sl)
        s += p[(size_t)sl * (Bsz * Nsz)];

    __shared__ float sv[Nsz];
    sv[n] = s;
    __syncthreads();

    const int sidx = n & 15;
    float msq = 0.f;
#pragma unroll
    for (int u = 0; u < 32; ++u) {
        float v = sv[u * 16 + sidx];
        msq += v * v;
    }
    const float mag   = sqrtf(msq);
    const float scale = mag / (1.0f + msq);
    out[(size_t)b * Nsz + n] = s * scale;
}

// ---------------------------------------------------------------------------
extern "C" void kernel_launch(void* const* d_in, const int* in_sizes, int n_in,
                              void* d_out, int out_size) {
    const float* x = (const float*)d_in[0];   // (256, 128, 1024) fp32
    const float* W = (const float*)d_in[1];   // (1, 1024, 32, 16, 128) fp32
    float* out = (float*)d_out;               // (256, 32, 16, 1) fp32

    static bool attr_done = false;
    if (!attr_done) {
        cudaFuncSetAttribute(k_gemm_mma, cudaFuncAttributeMaxDynamicSharedMemorySize,
                             SMEM_BYTES);
        attr_done = true;
    }

    dim3 tgrid(Csz / 32, Isz / 32, Bsz);      // (32, 4, 256)
    k_transpose<<<tgrid, dim3(32, 8)>>>(x);

    dim3 ggrid(Bsz / BM, Nsz / BN, NSPLIT);   // (2, 2, 32) = 128 CTAs
    k_gemm_mma<<<ggrid, 256, SMEM_BYTES>>>(W);

    k_reduce_squash<<<Bsz, Nsz>>>(out);
}

// round 16
// speedup vs baseline: 1.5767x; 1.0723x over previous
#include <cuda_runtime.h>
#include <cuda_fp16.h>
#include <cstdint>

// Problem constants
#define Bsz 256      // batch (GEMM M)
#define Isz 128      // in_units
#define Csz 1024     // in_channels
#define Nsz 512      // U*S (GEMM N)
#define NSPLIT 37    // ragged split-K -> grid (2,2,37) = 148 CTAs = 148 SMs
#define BK 32        // k per stage (2 x k16 MMA steps); 4 stages per c

// CTA tile 128x256, 8 warps (2x4), warp tile 64x64
#define BM 128
#define BN 256

// smem rows padded to 40 halfs (80 B) -> conflict-free fragment loads
#define RSTRIDE 40
#define A_HALFS (BM * RSTRIDE)              // 5120
#define B_HALFS (BN * RSTRIDE)              // 10240
#define STG_HALFS (A_HALFS + B_HALFS)       // 15360
#define SMEM_BYTES (2 * STG_HALFS * 2)      // 61440

// Scratch (static device globals — no runtime allocation)
__device__ __half g_xh[(size_t)Bsz * Csz * Isz];       // x^T (b, c, i) in fp16
__device__ float  g_part[(size_t)NSPLIT * Bsz * Nsz];  // split-K partials

// ---------------------------------------------------------------------------
// Helpers (sm_70/80-era PTX only — target is compute_103 WITHOUT 'a')
// ---------------------------------------------------------------------------
__device__ __forceinline__ uint32_t smem_u32(const void* p) {
    uint32_t a;
    asm("{ .reg .u64 t; cvta.to.shared.u64 t, %1; cvt.u32.u64 %0, t; }" : "=r"(a) : "l"(p));
    return a;
}

#define CP_ASYNC16(dst, src) \
    asm volatile("cp.async.cg.shared.global [%0], [%1], 16;" :: "r"(dst), "l"(src))
#define CP_COMMIT()  asm volatile("cp.async.commit_group;" ::: "memory")
#define CP_WAIT(n)   asm volatile("cp.async.wait_group %0;" :: "n"(n) : "memory")

// m16n8k16 fp16 MMA, fp32 accumulate (sm_70 base PTX)
#define MMA_F16(c, a, b) \
    asm volatile( \
        "mma.sync.aligned.m16n8k16.row.col.f32.f16.f16.f32 " \
        "{%0,%1,%2,%3}, {%4,%5,%6,%7}, {%8,%9}, {%0,%1,%2,%3};" \
        : "+f"((c)[0]), "+f"((c)[1]), "+f"((c)[2]), "+f"((c)[3]) \
        : "r"((a)[0]), "r"((a)[1]), "r"((a)[2]), "r"((a)[3]), \
          "r"((b)[0]), "r"((b)[1]))

// ---------------------------------------------------------------------------
// Kernel 1: per-batch transpose x (B, I, C) -> xh (B, C, I) in fp16
//   32x32 tile, 33-float padded rows: both phases bank-conflict-free.
// ---------------------------------------------------------------------------
__global__ void k_transpose(const float* __restrict__ x) {
    __shared__ float tile[32][33];
    int b  = blockIdx.z;
    int c0 = blockIdx.x * 32;
    int i0 = blockIdx.y * 32;
    const float* xb  = x    + (size_t)b * Isz * Csz;
    __half*      xtb = g_xh + (size_t)b * Csz * Isz;
    int tx = threadIdx.x, ty = threadIdx.y;
#pragma unroll
    for (int j = 0; j < 32; j += 8)
        tile[ty + j][tx] = xb[(size_t)(i0 + ty + j) * Csz + (c0 + tx)];
    __syncthreads();
#pragma unroll
    for (int j = 0; j < 32; j += 8)
        xtb[(size_t)(c0 + ty + j) * Isz + (i0 + tx)] = __float2half_rn(tile[tx][ty + j]);
}

// ---------------------------------------------------------------------------
// Kernel 2: ragged split-K fp16 GEMM via mma.sync m16n8k16 (fp32 accum)
//   grid = (2 m, 2 n, 37 slices) = 148 CTAs = one CTA per SM.
//   Slice z covers c in [z*1024/37, (z+1)*1024/37) -> 27 or 28 c-values,
//   nstage = 4 * c_count (runtime bound; inner loops fully unrolled).
// ---------------------------------------------------------------------------
__global__ __launch_bounds__(256, 1)
void k_gemm_mma(const float* __restrict__ W) {
    extern __shared__ __half sm[];
    const uint32_t smem_base = smem_u32(sm);

    const int tid  = threadIdx.x;
    const int wid  = tid >> 5;
    const int lane = tid & 31;
    const int g    = lane >> 2;   // group id (0..7)
    const int t    = lane & 3;    // thread-in-group

    const int warp_m = wid & 1;   // 0..1 -> 64-row block
    const int warp_n = wid >> 1;  // 0..3 -> 64-col block

    const int m0 = blockIdx.x * BM;
    const int n0 = blockIdx.y * BN;
    const int z  = blockIdx.z;
    const int c_begin = (z * Csz) / NSPLIT;
    const int c_end   = ((z + 1) * Csz) / NSPLIT;
    const int nstage  = (c_end - c_begin) * 4;   // 108 or 112

    const __half* aBase = g_xh + (size_t)m0 * (Csz * Isz) + (size_t)c_begin * Isz;
    const float*  wBase = W + (size_t)c_begin * (Nsz * Isz) + (size_t)n0 * Isz;

    // A loader indices: 128 rows x 4 chunks of 16B (8 halfs)
    const int a_row = tid >> 2;   // 0..63 (+64 on j=1)
    const int a_ch  = tid & 3;    // 16B chunk
    // B loader indices: 256 rows x 8 chunks of float4 (4 floats -> 4 halfs)
    const int b_row = tid >> 3;   // 0..31 (+32*j)
    const int b_ch  = tid & 7;

    auto a_issue = [&](int st, int bf) {
        const uint32_t dA = smem_base + (uint32_t)(bf * STG_HALFS) * 2;
        const __half* asrc = aBase + st * BK;
#pragma unroll
        for (int j = 0; j < 2; j++) {
            int r = a_row + j * 64;
            uint32_t so = (uint32_t)(r * RSTRIDE + a_ch * 8) * 2;
            CP_ASYNC16(dA + so, asrc + (size_t)r * (Csz * Isz) + a_ch * 8);
        }
        CP_COMMIT();
    };

    float4 bpf[8];
    auto b_ldg = [&](int st) {
        const float* bsrc = wBase + (size_t)(st >> 2) * (Nsz * Isz) + (st & 3) * BK;
#pragma unroll
        for (int j = 0; j < 8; j++) {
            int r = b_row + j * 32;
            bpf[j] = *(const float4*)(bsrc + (size_t)r * Isz + b_ch * 4);
        }
    };
    auto b_sts = [&](int bf) {
        __half* dB = sm + bf * STG_HALFS + A_HALFS;
#pragma unroll
        for (int j = 0; j < 8; j++) {
            int r = b_row + j * 32;
            __half2 p0 = __floats2half2_rn(bpf[j].x, bpf[j].y);
            __half2 p1 = __floats2half2_rn(bpf[j].z, bpf[j].w);
            *(__half2*)(dB + r * RSTRIDE + b_ch * 4)     = p0;
            *(__half2*)(dB + r * RSTRIDE + b_ch * 4 + 2) = p1;
        }
    };

    float acc[4][8][4];
#pragma unroll
    for (int mt = 0; mt < 4; mt++)
#pragma unroll
        for (int nt = 0; nt < 8; nt++)
#pragma unroll
            for (int e = 0; e < 4; e++) acc[mt][nt][e] = 0.f;

    // prologue: stage 0
    b_ldg(0);
    a_issue(0, 0);
    b_sts(0);
    CP_WAIT(0);
    __syncthreads();
    int buf = 0;

    for (int st = 0; st < nstage; ++st) {
        const bool has_next = (st + 1 < nstage);
        if (has_next) {
            b_ldg(st + 1);            // LDG latency overlapped by compute below
            a_issue(st + 1, buf ^ 1);
        }

        const __half* cA = sm + buf * STG_HALFS;
        const __half* cB = cA + A_HALFS;

#pragma unroll
        for (int kk = 0; kk < 2; ++kk) {
            const int kb = kk * 16;
            uint32_t af[4][4];
#pragma unroll
            for (int mt = 0; mt < 4; mt++) {
                const int r0 = warp_m * 64 + mt * 16 + g;
                const __half* p0 = cA + r0 * RSTRIDE + kb + 2 * t;
                const __half* p1 = cA + (r0 + 8) * RSTRIDE + kb + 2 * t;
                af[mt][0] = *(const uint32_t*)p0;
                af[mt][1] = *(const uint32_t*)p1;
                af[mt][2] = *(const uint32_t*)(p0 + 8);
                af[mt][3] = *(const uint32_t*)(p1 + 8);
            }
            uint32_t bfr[8][2];
#pragma unroll
            for (int nt = 0; nt < 8; nt++) {
                const int nn = warp_n * 64 + nt * 8 + g;
                const __half* p = cB + nn * RSTRIDE + kb + 2 * t;
                bfr[nt][0] = *(const uint32_t*)p;
                bfr[nt][1] = *(const uint32_t*)(p + 8);
            }
#pragma unroll
            for (int mt = 0; mt < 4; mt++)
#pragma unroll
                for (int nt = 0; nt < 8; nt++)
                    MMA_F16(acc[mt][nt], af[mt], bfr[nt]);
        }

        if (has_next) {
            b_sts(buf ^ 1);
            CP_WAIT(0);
        }
        __syncthreads();
        buf ^= 1;
    }

    // epilogue: deterministic partial writes
    float* dst = g_part + (size_t)z * (Bsz * Nsz);
#pragma unroll
    for (int mt = 0; mt < 4; mt++) {
        const int m = m0 + warp_m * 64 + mt * 16 + g;
#pragma unroll
        for (int nt = 0; nt < 8; nt++) {
            const int n = n0 + warp_n * 64 + nt * 8 + 2 * t;
            *(float2*)&dst[(size_t)m * Nsz + n] =
                make_float2(acc[mt][nt][0], acc[mt][nt][1]);
            *(float2*)&dst[(size_t)(m + 8) * Nsz + n] =
                make_float2(acc[mt][nt][2], acc[mt][nt][3]);
        }
    }
}

// ---------------------------------------------------------------------------
// Kernel 3: reduce over split-K slices + squash epilogue
// ---------------------------------------------------------------------------
__global__ void k_reduce_squash(float* __restrict__ out) {
    const int b = blockIdx.x;
    const int n = threadIdx.x;  // 0..511
    float s = 0.f;
    const float* p = g_part + (size_t)b * Nsz + n;
#pragma unroll
    for (int sl = 0; sl < NSPLIT; ++sl)
        s += p[(size_t)sl * (Bsz * Nsz)];

    __shared__ float sv[Nsz];
    sv[n] = s;
    __syncthreads();

    const int sidx = n & 15;
    float msq = 0.f;
#pragma unroll
    for (int u = 0; u < 32; ++u) {
        float v = sv[u * 16 + sidx];
        msq += v * v;
    }
    const float mag   = sqrtf(msq);
    const float scale = mag / (1.0f + msq);
    out[(size_t)b * Nsz + n] = s * scale;
}

// ---------------------------------------------------------------------------
extern "C" void kernel_launch(void* const* d_in, const int* in_sizes, int n_in,
                              void* d_out, int out_size) {
    const float* x = (const float*)d_in[0];   // (256, 128, 1024) fp32
    const float* W = (const float*)d_in[1];   // (1, 1024, 32, 16, 128) fp32
    float* out = (float*)d_out;               // (256, 32, 16, 1) fp32

    static bool attr_done = false;
    if (!attr_done) {
        cudaFuncSetAttribute(k_gemm_mma, cudaFuncAttributeMaxDynamicSharedMemorySize,
                             SMEM_BYTES);
        attr_done = true;
    }

    dim3 tgrid(Csz / 32, Isz / 32, Bsz);      // (32, 4, 256)
    k_transpose<<<tgrid, dim3(32, 8)>>>(x);

    dim3 ggrid(Bsz / BM, Nsz / BN, NSPLIT);   // (2, 2, 37) = 148 CTAs
    k_gemm_mma<<<ggrid, 256, SMEM_BYTES>>>(W);

    k_reduce_squash<<<Bsz, Nsz>>>(out);
}

// round 17
// speedup vs baseline: 1.6155x; 1.0246x over previous
#include <cuda_runtime.h>
#include <cuda_fp16.h>
#include <cstdint>

// Problem constants
#define Bsz 256      // batch (GEMM M)
#define Isz 128      // in_units
#define Csz 1024     // in_channels
#define Nsz 512      // U*S (GEMM N)
#define NSPLIT 37    // ragged split-K -> grid (2,2,37) = 148 CTAs = 148 SMs
#define BK 32        // k per stage (2 x k16 MMA steps); 4 stages per c

// CTA tile 128x256, 8 warps (2x4), warp tile 64x64
#define BM 128
#define BN 256

// smem rows padded to 40 halfs (80 B) -> conflict-free fragment loads
#define RSTRIDE 40
#define A_HALFS (BM * RSTRIDE)              // 5120
#define B_HALFS (BN * RSTRIDE)              // 10240
#define STG_HALFS (A_HALFS + B_HALFS)       // 15360
#define SMEM_BYTES (2 * STG_HALFS * 2)      // 61440

// Scratch (static device globals — no runtime allocation)
__device__ __half g_xh[(size_t)Bsz * Csz * Isz];       // x^T (b, c, i) in fp16
__device__ float  g_part[(size_t)NSPLIT * Bsz * Nsz];  // split-K partials

// ---------------------------------------------------------------------------
// Helpers (sm_70/80-era PTX only — target is compute_103 WITHOUT 'a')
// ---------------------------------------------------------------------------
__device__ __forceinline__ uint32_t smem_u32(const void* p) {
    uint32_t a;
    asm("{ .reg .u64 t; cvta.to.shared.u64 t, %1; cvt.u32.u64 %0, t; }" : "=r"(a) : "l"(p));
    return a;
}

#define CP_ASYNC16(dst, src) \
    asm volatile("cp.async.cg.shared.global [%0], [%1], 16;" :: "r"(dst), "l"(src))
#define CP_COMMIT()  asm volatile("cp.async.commit_group;" ::: "memory")
#define CP_WAIT(n)   asm volatile("cp.async.wait_group %0;" :: "n"(n) : "memory")

// m16n8k16 fp16 MMA, fp32 accumulate (sm_70 base PTX)
#define MMA_F16(c, a, b) \
    asm volatile( \
        "mma.sync.aligned.m16n8k16.row.col.f32.f16.f16.f32 " \
        "{%0,%1,%2,%3}, {%4,%5,%6,%7}, {%8,%9}, {%0,%1,%2,%3};" \
        : "+f"((c)[0]), "+f"((c)[1]), "+f"((c)[2]), "+f"((c)[3]) \
        : "r"((a)[0]), "r"((a)[1]), "r"((a)[2]), "r"((a)[3]), \
          "r"((b)[0]), "r"((b)[1]))

// ---------------------------------------------------------------------------
// Kernel 1: per-batch transpose x (B, I, C) -> xh (B, C, I) in fp16
//   Tile: 32 c x 128 i (full i extent). 256 threads.
//   Load:  float4 LDG (4 per thread, coalesced 128 B rows).
//   Store: each thread packs 8 consecutive i into one uint4 (16 B) STG ->
//          full-width store transactions. LDS conflicts bounded at 4-way
//          (non-binding vs DRAM budget).
// ---------------------------------------------------------------------------
#define TPAD 33
__global__ void k_transpose(const float* __restrict__ x) {
    __shared__ float tile[Isz][TPAD];   // [i][c], 32 c used
    const int b  = blockIdx.y;
    const int c0 = blockIdx.x * 32;
    const float* xb  = x    + (size_t)b * Isz * Csz + c0;
    __half*      xtb = g_xh + (size_t)b * Csz * Isz;
    const int tid = threadIdx.x;

    // load: 128 rows x 8 float4; thread -> (i = tid>>3 (+32*p), j = tid&7)
    const int li = tid >> 3;          // 0..31
    const int lj = tid & 7;           // float4 within 32-float row
#pragma unroll
    for (int p = 0; p < 4; p++) {
        const int i = li + p * 32;
        float4 v = *(const float4*)(xb + (size_t)i * Csz + lj * 4);
        tile[i][lj * 4 + 0] = v.x;
        tile[i][lj * 4 + 1] = v.y;
        tile[i][lj * 4 + 2] = v.z;
        tile[i][lj * 4 + 3] = v.w;
    }
    __syncthreads();

    // store: 32 c-rows of 128 halfs; thread -> (c2 = tid>>4, q = tid&15)
    // each thread handles c = c2 + 16*cp for cp in {0,1}; 8 i per uint4
    const int c2 = tid >> 4;          // 0..15
    const int q  = tid & 15;          // 0..15 -> i0 = 8q
#pragma unroll
    for (int cp = 0; cp < 2; cp++) {
        const int cc = c2 + cp * 16;
        const int i0 = q * 8;
        __half2 h[4];
#pragma unroll
        for (int r = 0; r < 4; r++)
            h[r] = __floats2half2_rn(tile[i0 + 2 * r][cc], tile[i0 + 2 * r + 1][cc]);
        *(uint4*)(xtb + (size_t)(c0 + cc) * Isz + i0) = *(uint4*)h;
    }
}

// ---------------------------------------------------------------------------
// Kernel 2: ragged split-K fp16 GEMM via mma.sync m16n8k16 (fp32 accum)
//   grid = (2 m, 2 n, 37 slices) = 148 CTAs = one CTA per SM.
//   Slice z covers c in [z*1024/37, (z+1)*1024/37) -> 27 or 28 c-values,
//   nstage = 4 * c_count (runtime bound; inner loops fully unrolled).
// ---------------------------------------------------------------------------
__global__ __launch_bounds__(256, 1)
void k_gemm_mma(const float* __restrict__ W) {
    extern __shared__ __half sm[];
    const uint32_t smem_base = smem_u32(sm);

    const int tid  = threadIdx.x;
    const int wid  = tid >> 5;
    const int lane = tid & 31;
    const int g    = lane >> 2;   // group id (0..7)
    const int t    = lane & 3;    // thread-in-group

    const int warp_m = wid & 1;   // 0..1 -> 64-row block
    const int warp_n = wid >> 1;  // 0..3 -> 64-col block

    const int m0 = blockIdx.x * BM;
    const int n0 = blockIdx.y * BN;
    const int z  = blockIdx.z;
    const int c_begin = (z * Csz) / NSPLIT;
    const int c_end   = ((z + 1) * Csz) / NSPLIT;
    const int nstage  = (c_end - c_begin) * 4;   // 108 or 112

    const __half* aBase = g_xh + (size_t)m0 * (Csz * Isz) + (size_t)c_begin * Isz;
    const float*  wBase = W + (size_t)c_begin * (Nsz * Isz) + (size_t)n0 * Isz;

    // A loader indices: 128 rows x 4 chunks of 16B (8 halfs)
    const int a_row = tid >> 2;   // 0..63 (+64 on j=1)
    const int a_ch  = tid & 3;    // 16B chunk
    // B loader indices: 256 rows x 8 chunks of float4 (4 floats -> 4 halfs)
    const int b_row = tid >> 3;   // 0..31 (+32*j)
    const int b_ch  = tid & 7;

    auto a_issue = [&](int st, int bf) {
        const uint32_t dA = smem_base + (uint32_t)(bf * STG_HALFS) * 2;
        const __half* asrc = aBase + st * BK;
#pragma unroll
        for (int j = 0; j < 2; j++) {
            int r = a_row + j * 64;
            uint32_t so = (uint32_t)(r * RSTRIDE + a_ch * 8) * 2;
            CP_ASYNC16(dA + so, asrc + (size_t)r * (Csz * Isz) + a_ch * 8);
        }
        CP_COMMIT();
    };

    float4 bpf[8];
    auto b_ldg = [&](int st) {
        const float* bsrc = wBase + (size_t)(st >> 2) * (Nsz * Isz) + (st & 3) * BK;
#pragma unroll
        for (int j = 0; j < 8; j++) {
            int r = b_row + j * 32;
            bpf[j] = *(const float4*)(bsrc + (size_t)r * Isz + b_ch * 4);
        }
    };
    auto b_sts = [&](int bf) {
        __half* dB = sm + bf * STG_HALFS + A_HALFS;
#pragma unroll
        for (int j = 0; j < 8; j++) {
            int r = b_row + j * 32;
            __half2 p0 = __floats2half2_rn(bpf[j].x, bpf[j].y);
            __half2 p1 = __floats2half2_rn(bpf[j].z, bpf[j].w);
            *(__half2*)(dB + r * RSTRIDE + b_ch * 4)     = p0;
            *(__half2*)(dB + r * RSTRIDE + b_ch * 4 + 2) = p1;
        }
    };

    float acc[4][8][4];
#pragma unroll
    for (int mt = 0; mt < 4; mt++)
#pragma unroll
        for (int nt = 0; nt < 8; nt++)
#pragma unroll
            for (int e = 0; e < 4; e++) acc[mt][nt][e] = 0.f;

    // prologue: stage 0
    b_ldg(0);
    a_issue(0, 0);
    b_sts(0);
    CP_WAIT(0);
    __syncthreads();
    int buf = 0;

    for (int st = 0; st < nstage; ++st) {
        const bool has_next = (st + 1 < nstage);
        if (has_next) {
            b_ldg(st + 1);            // LDG latency overlapped by compute below
            a_issue(st + 1, buf ^ 1);
        }

        const __half* cA = sm + buf * STG_HALFS;
        const __half* cB = cA + A_HALFS;

#pragma unroll
        for (int kk = 0; kk < 2; ++kk) {
            const int kb = kk * 16;
            uint32_t af[4][4];
#pragma unroll
            for (int mt = 0; mt < 4; mt++) {
                const int r0 = warp_m * 64 + mt * 16 + g;
                const __half* p0 = cA + r0 * RSTRIDE + kb + 2 * t;
                const __half* p1 = cA + (r0 + 8) * RSTRIDE + kb + 2 * t;
                af[mt][0] = *(const uint32_t*)p0;
                af[mt][1] = *(const uint32_t*)p1;
                af[mt][2] = *(const uint32_t*)(p0 + 8);
                af[mt][3] = *(const uint32_t*)(p1 + 8);
            }
            uint32_t bfr[8][2];
#pragma unroll
            for (int nt = 0; nt < 8; nt++) {
                const int nn = warp_n * 64 + nt * 8 + g;
                const __half* p = cB + nn * RSTRIDE + kb + 2 * t;
                bfr[nt][0] = *(const uint32_t*)p;
                bfr[nt][1] = *(const uint32_t*)(p + 8);
            }
#pragma unroll
            for (int mt = 0; mt < 4; mt++)
#pragma unroll
                for (int nt = 0; nt < 8; nt++)
                    MMA_F16(acc[mt][nt], af[mt], bfr[nt]);
        }

        if (has_next) {
            b_sts(buf ^ 1);
            CP_WAIT(0);
        }
        __syncthreads();
        buf ^= 1;
    }

    // epilogue: deterministic partial writes
    float* dst = g_part + (size_t)z * (Bsz * Nsz);
#pragma unroll
    for (int mt = 0; mt < 4; mt++) {
        const int m = m0 + warp_m * 64 + mt * 16 + g;
#pragma unroll
        for (int nt = 0; nt < 8; nt++) {
            const int n = n0 + warp_n * 64 + nt * 8 + 2 * t;
            *(float2*)&dst[(size_t)m * Nsz + n] =
                make_float2(acc[mt][nt][0], acc[mt][nt][1]);
            *(float2*)&dst[(size_t)(m + 8) * Nsz + n] =
                make_float2(acc[mt][nt][2], acc[mt][nt][3]);
        }
    }
}

// ---------------------------------------------------------------------------
// Kernel 3: reduce over split-K slices + squash epilogue
// ---------------------------------------------------------------------------
__global__ void k_reduce_squash(float* __restrict__ out) {
    const int b = blockIdx.x;
    const int n = threadIdx.x;  // 0..511
    float s = 0.f;
    const float* p = g_part + (size_t)b * Nsz + n;
#pragma unroll
    for (int sl = 0; sl < NSPLIT; ++sl)
        s += p[(size_t)sl * (Bsz * Nsz)];

    __shared__ float sv[Nsz];
    sv[n] = s;
    __syncthreads();

    const int sidx = n & 15;
    float msq = 0.f;
#pragma unroll
    for (int u = 0; u < 32; ++u) {
        float v = sv[u * 16 + sidx];
        msq += v * v;
    }
    const float mag   = sqrtf(msq);
    const float scale = mag / (1.0f + msq);
    out[(size_t)b * Nsz + n] = s * scale;
}

// ---------------------------------------------------------------------------
extern "C" void kernel_launch(void* const* d_in, const int* in_sizes, int n_in,
                              void* d_out, int out_size) {
    const float* x = (const float*)d_in[0];   // (256, 128, 1024) fp32
    const float* W = (const float*)d_in[1];   // (1, 1024, 32, 16, 128) fp32
    float* out = (float*)d_out;               // (256, 32, 16, 1) fp32

    static bool attr_done = false;
    if (!attr_done) {
        cudaFuncSetAttribute(k_gemm_mma, cudaFuncAttributeMaxDynamicSharedMemorySize,
                             SMEM_BYTES);
        attr_done = true;
    }

    dim3 tgrid(Csz / 32, Bsz);                // (32, 256) = 8192 blocks
    k_transpose<<<tgrid, 256>>>(x);

    dim3 ggrid(Bsz / BM, Nsz / BN, NSPLIT);   // (2, 2, 37) = 148 CTAs
    k_gemm_mma<<<ggrid, 256, SMEM_BYTES>>>(W);

    k_reduce_squash<<<Bsz, Nsz>>>(out);
}